// round 9
// baseline (speedup 1.0000x reference)
#include <cuda_runtime.h>
#include <cstdint>

// Shapes: x:(16384,4096) f32, latency:(16384) f32, W:(4096,1536) f32,
// b:(1536) f32, u:(16384,24,32,2) f32  -> out:(16384,32,2,32) f32
#define NB      16384
#define HID     4096
#define NCOLS   768
#define NGROUPS 384
#define MARGIN  1e-4f

// tcgen05 path config
#define BM 128
#define BN 128
#define KC 32                 // fp32 elems per K-chunk (128B rows, SW128)
#define NCHUNK (HID / KC)     // 128
#define STAGES 3
#define STAGE_BYTES 65536     // Ahi 16K | Alo 16K | Bhi 16K | Blo 16K
#define DSMEM_BYTES (STAGES * STAGE_BYTES + 1024)

// Device-pass feature gate: tcgen05 exists only in arch-specific sm_10xa passes.
#if defined(__CUDA_ARCH_FEAT_SM103_ALL) || defined(__CUDA_ARCH_FEAT_SM100_ALL) || \
    defined(__CUDA_ARCH_FEAT_SM101_ALL)
#define TC_PATH 1
#endif

__device__ float g_Bhi[(size_t)NCOLS * HID];   // dW hi (tf32), [n][k]
__device__ float g_Blo[(size_t)NCOLS * HID];   // dW lo (tf32), [n][k]
__device__ float g_dW [(size_t)HID * NCOLS];   // dW fp32,      [k][n] (fallback GEMM)
__device__ float g_dWn[(size_t)NCOLS * HID];   // dW fp32,      [n][k] (exact repair)
__device__ float g_scores[(size_t)NB * NGROUPS];

// ---------------------------------------------------------------- helpers
__device__ __forceinline__ uint32_t tf32_rna(float x) {
    uint32_t r; asm("cvt.rna.tf32.f32 %0, %1;" : "=r"(r) : "f"(x)); return r;
}
__device__ __forceinline__ unsigned long long pack2(float lo, float hi) {
    unsigned long long r;
    asm("mov.b64 %0, {%1, %2};" : "=l"(r) : "f"(lo), "f"(hi));
    return r;
}
__device__ __forceinline__ void fma2(unsigned long long& d,
                                     unsigned long long a, unsigned long long b) {
    asm("fma.rn.f32x2 %0, %1, %2, %0;" : "+l"(d) : "l"(a), "l"(b));
}
__device__ __forceinline__ float2 unpack2(unsigned long long v) {
    float2 r;
    asm("mov.b64 {%0, %1}, %2;" : "=f"(r.x), "=f"(r.y) : "l"(v));
    return r;
}
__device__ __forceinline__ float gum(float v) {
    float t = v * (1.0f - 2e-6f) + 1e-6f;
    return -logf(-logf(t));
}
__device__ __forceinline__ float sigp(float dl, float u0, float u1) {
    float z = (dl + gum(u0) - gum(u1)) * 0.2f;
    return 1.0f / (1.0f + __expf(-z));
}

#ifdef TC_PATH
__device__ __forceinline__ uint32_t smem_u32(const void* p) {
    uint32_t a;
    asm("{ .reg .u64 t; cvta.to.shared.u64 t, %1; cvt.u32.u64 %0, t; }"
        : "=r"(a) : "l"(p));
    return a;
}
__device__ __forceinline__ uint32_t elect1() {
    uint32_t p;
    asm volatile("{\n\t.reg .pred p;\n\telect.sync _|p, 0xFFFFFFFF;\n\t"
                 "selp.b32 %0, 1, 0, p;\n\t}" : "=r"(p));
    return p;
}
#define SW(o) ((uint32_t)(o) ^ ((((uint32_t)(o)) >> 3) & 0x70u))
#define MBAR_INIT(a, c) \
    asm volatile("mbarrier.init.shared.b64 [%0], %1;" :: "r"(a), "r"(c) : "memory")
#define MBAR_ARRIVE(a) \
    asm volatile("mbarrier.arrive.shared.b64 _, [%0];" :: "r"(a) : "memory")
__device__ __forceinline__ void mbar_wait(uint32_t a, uint32_t ph) {
    asm volatile(
        "{\n\t.reg .pred P;\n\t"
        "WL_%=:\n\t"
        "mbarrier.try_wait.parity.acquire.cta.shared::cta.b64 P, [%0], %1, 0x989680;\n\t"
        "@P bra.uni WD_%=;\n\t"
        "bra.uni WL_%=;\n\t"
        "WD_%=:\n\t}"
        :: "r"(a), "r"(ph) : "memory");
}
#define FENCE_ASYNC() asm volatile("fence.proxy.async.shared::cta;" ::: "memory")
#define TC_COMMIT(a) \
    asm volatile("tcgen05.commit.cta_group::1.mbarrier::arrive::one.shared::cluster.b64 [%0];" \
                 :: "r"(a) : "memory")
#define TC_WAIT_LD() asm volatile("tcgen05.wait::ld.sync.aligned;" ::: "memory")

static constexpr unsigned long long DESC_BASE =
    (2ull << 61) | (1ull << 46) | (64ull << 32) | (1ull << 16);  // SW128 K-major
__device__ __forceinline__ uint64_t mk_desc(uint32_t addr) {
    return DESC_BASE | ((addr >> 4) & 0x3FFFull);
}
// SS tf32 MMA, cta_group::1. idesc: c=f32, a=b=tf32, M=128, N=128.
__device__ __forceinline__ void mma_tf32(uint32_t d, uint64_t a, uint64_t b,
                                         uint32_t idesc, uint32_t en) {
    asm volatile(
        "{\n\t.reg .pred p;\n\tsetp.ne.u32 p, %4, 0;\n\t"
        "tcgen05.mma.cta_group::1.kind::tf32 [%0], %1, %2, %3, {%5,%5,%5,%5}, p;\n\t}"
        :: "r"(d), "l"(a), "l"(b), "r"(idesc), "r"(en), "r"(0u) : "memory");
}
#define LDTM32(r, addr) \
    asm volatile( \
        "tcgen05.ld.sync.aligned.32x32b.x32.b32 " \
        "{%0, %1, %2, %3, %4, %5, %6, %7, " \
        " %8, %9, %10, %11, %12, %13, %14, %15, " \
        " %16, %17, %18, %19, %20, %21, %22, %23, " \
        " %24, %25, %26, %27, %28, %29, %30, %31}, [%32];" \
        : "=r"((r)[0]),  "=r"((r)[1]),  "=r"((r)[2]),  "=r"((r)[3]), \
          "=r"((r)[4]),  "=r"((r)[5]),  "=r"((r)[6]),  "=r"((r)[7]), \
          "=r"((r)[8]),  "=r"((r)[9]),  "=r"((r)[10]), "=r"((r)[11]), \
          "=r"((r)[12]), "=r"((r)[13]), "=r"((r)[14]), "=r"((r)[15]), \
          "=r"((r)[16]), "=r"((r)[17]), "=r"((r)[18]), "=r"((r)[19]), \
          "=r"((r)[20]), "=r"((r)[21]), "=r"((r)[22]), "=r"((r)[23]), \
          "=r"((r)[24]), "=r"((r)[25]), "=r"((r)[26]), "=r"((r)[27]), \
          "=r"((r)[28]), "=r"((r)[29]), "=r"((r)[30]), "=r"((r)[31]) \
        : "r"(addr))
#endif  // TC_PATH

// ---------------------------------------------------------------------------
// Kernel A: dW = W[:,even]-W[:,odd]; tf32 hi/lo [n][k], fp32 [k][n] + [n][k].
// ---------------------------------------------------------------------------
__global__ void prep_dw_kernel(const float* __restrict__ W) {
    size_t idx = (size_t)blockIdx.x * 256 + threadIdx.x;
    if (idx >= (size_t)HID * NCOLS) return;
    int k = (int)(idx / NCOLS);
    int n = (int)(idx - (size_t)k * NCOLS);
    const float* wr = W + (size_t)k * (2 * NCOLS) + 2 * n;
    float d = wr[0] - wr[1];
    g_dW[idx] = d;                                    // [k][n], coalesced
    uint32_t h = tf32_rna(d);
    float hf = __uint_as_float(h);
    uint32_t l = tf32_rna(d - hf);
    size_t tn = (size_t)n * HID + k;                  // [n][k]
    g_Bhi[tn] = hf;
    g_Blo[tn] = __uint_as_float(l);
    g_dWn[tn] = d;
}

// ---------------------------------------------------------------------------
// Kernel B: GEMM + fused gumbel/sigmoid/pair-mean epilogue -> g_scores.
//   TC_PATH:  warp-specialized tcgen05 tf32 3-product (hi*hi + hi*lo + lo*hi)
//   fallback: proven SIMT f32x2 GEMM (round-5)
// ---------------------------------------------------------------------------
__global__ void
#ifdef TC_PATH
__launch_bounds__(256, 1)
#else
__launch_bounds__(256, 2)
#endif
gemm_score_kernel(const float* __restrict__ x,
                  const float* __restrict__ bias,
                  const float* __restrict__ u) {
#ifdef TC_PATH
    extern __shared__ char dsm_raw[];
    char* dbase = (char*)((((uintptr_t)dsm_raw) + 1023) & ~(uintptr_t)1023);
    const uint32_t dyn = smem_u32(dbase);

    __shared__ uint32_t s_tmem;
    __shared__ __align__(8) unsigned long long s_mbar[10];
    __shared__ float s_db[BN];

    const int tid = threadIdx.x;
    const int wid = tid >> 5;
    const int bi  = blockIdx.x;
    const int bm  = (bi / (NCOLS / BN)) * BM;
    const int bn  = (bi % (NCOLS / BN)) * BN;
    const uint32_t mb0 = smem_u32(s_mbar);
    // mbars: [0..2]=a_full(128) [3..5]=b_full(64) [6..8]=done(1) [9]=final(1)

    if (tid == 0) {
        for (int s = 0; s < 3; s++) {
            MBAR_INIT(mb0 + 8 * s, 128);
            MBAR_INIT(mb0 + 8 * (3 + s), 64);
            MBAR_INIT(mb0 + 8 * (6 + s), 1);
        }
        MBAR_INIT(mb0 + 8 * 9, 1);
    }
    if (wid == 4) {
        asm volatile("tcgen05.alloc.cta_group::1.sync.aligned.shared::cta.b32 [%0], %1;"
                     :: "r"(smem_u32(&s_tmem)), "r"(128) : "memory");
        asm volatile("tcgen05.relinquish_alloc_permit.cta_group::1.sync.aligned;");
    }
    if (tid < BN) {
        int n = bn + tid;
        s_db[tid] = bias[2 * n] - bias[2 * n + 1];
    }
    __syncthreads();
    const uint32_t tmem = s_tmem;

    if (wid < 4) {
        // ---- A producer: 128 threads, x tile 128 rows x 32 cols per chunk
        const int kq = tid & 7;
        const int r0 = tid >> 3;
        int st = 0, ph = 1;
        for (int c = 0; c < NCHUNK; c++) {
            mbar_wait(mb0 + 8 * (6 + st), ph);   // stage free
            char* ahi = dbase + st * STAGE_BYTES;
            char* alo = ahi + 16384;
            const int k0 = c * KC;
#pragma unroll
            for (int p = 0; p < 8; p++) {
                int row = p * 16 + r0;
                float4 v = *(const float4*)(x + (size_t)(bm + row) * HID + k0 + kq * 4);
                uint32_t h0 = tf32_rna(v.x), h1 = tf32_rna(v.y);
                uint32_t h2 = tf32_rna(v.z), h3 = tf32_rna(v.w);
                uint32_t l0 = tf32_rna(v.x - __uint_as_float(h0));
                uint32_t l1 = tf32_rna(v.y - __uint_as_float(h1));
                uint32_t l2 = tf32_rna(v.z - __uint_as_float(h2));
                uint32_t l3 = tf32_rna(v.w - __uint_as_float(h3));
                uint32_t sw = SW(row * 128 + kq * 16);
                *(uint4*)(ahi + sw) = make_uint4(h0, h1, h2, h3);
                *(uint4*)(alo + sw) = make_uint4(l0, l1, l2, l3);
            }
            FENCE_ASYNC();
            MBAR_ARRIVE(mb0 + 8 * st);           // a_full
            if (++st == STAGES) { st = 0; ph ^= 1; }
        }
    } else if (wid == 4) {
        // ---- MMA warp
        const uint32_t IDESC = 0x8200910u;  // f32 acc, tf32 a/b, M=128, N=128
        const uint32_t leader = elect1();
        int st = 0, ph = 0;
        for (int c = 0; c < NCHUNK; c++) {
            mbar_wait(mb0 + 8 * st, ph);         // a_full
            mbar_wait(mb0 + 8 * (3 + st), ph);   // b_full
            if (leader) {
                uint32_t base = dyn + st * STAGE_BYTES;
                uint64_t ah = mk_desc(base);
                uint64_t al = mk_desc(base + 16384);
                uint64_t bh = mk_desc(base + 32768);
                uint64_t bl = mk_desc(base + 49152);
#pragma unroll
                for (int j = 0; j < 4; j++) {    // K=8 per MMA, 4 steps per chunk
                    uint64_t o = 2 * j;
                    mma_tf32(tmem, ah + o, bh + o, IDESC, !(c == 0 && j == 0));
                    mma_tf32(tmem, ah + o, bl + o, IDESC, 1u);
                    mma_tf32(tmem, al + o, bh + o, IDESC, 1u);
                }
                TC_COMMIT(mb0 + 8 * (6 + st));   // done -> stage reusable
            }
            if (++st == STAGES) { st = 0; ph ^= 1; }
        }
        if (leader) TC_COMMIT(mb0 + 8 * 9);      // final
    } else if (wid >= 6) {
        // ---- B producer: 64 threads, Bhi/Blo tiles per chunk
        const int t = tid - 192;
        int st = 0, ph = 1;
        for (int c = 0; c < NCHUNK; c++) {
            mbar_wait(mb0 + 8 * (6 + st), ph);
            char* bhs = dbase + st * STAGE_BYTES + 32768;
            char* bls = bhs + 16384;
            const int k0 = c * KC;
#pragma unroll
            for (int i = 0; i < 16; i++) {
                int unit = t + 64 * i;           // 0..1023
                int row = unit >> 3;
                int cu  = unit & 7;
                size_t g = (size_t)(bn + row) * HID + k0 + cu * 4;
                float4 vh = *(const float4*)(g_Bhi + g);
                float4 vl = *(const float4*)(g_Blo + g);
                uint32_t sw = SW(row * 128 + cu * 16);
                *(float4*)(bhs + sw) = vh;
                *(float4*)(bls + sw) = vl;
            }
            FENCE_ASYNC();
            MBAR_ARRIVE(mb0 + 8 * (3 + st));     // b_full
            if (++st == STAGES) { st = 0; ph ^= 1; }
        }
    }
    // wid==5 idle through mainloop

    __syncthreads();
    mbar_wait(mb0 + 8 * 9, 0);
    asm volatile("tcgen05.fence::after_thread_sync;" ::: "memory");

    if (wid < 4) {
        // ---- epilogue: thread owns row m = bm + tid (its warp subpartition)
        const int m = bm + tid;
        const float* up = u + (size_t)m * (2 * NCOLS) + 2 * bn;
        float* sp = g_scores + (size_t)m * NGROUPS + (bn >> 1);
#pragma unroll
        for (int cb = 0; cb < BN; cb += 32) {
            uint32_t d[32];
            LDTM32(d, tmem + cb);
            TC_WAIT_LD();
#pragma unroll
            for (int q = 0; q < 8; q++) {
                float4 u0 = *(const float4*)(up + 2 * cb + 8 * q);
                float4 u1 = *(const float4*)(up + 2 * cb + 8 * q + 4);
                int c0 = cb + 4 * q;
                float p0 = sigp(__uint_as_float(d[4 * q + 0]) + s_db[c0 + 0], u0.x, u0.y);
                float p1 = sigp(__uint_as_float(d[4 * q + 1]) + s_db[c0 + 1], u0.z, u0.w);
                float p2 = sigp(__uint_as_float(d[4 * q + 2]) + s_db[c0 + 2], u1.x, u1.y);
                float p3 = sigp(__uint_as_float(d[4 * q + 3]) + s_db[c0 + 3], u1.z, u1.w);
                *(float2*)(sp + (cb >> 1) + 2 * q) =
                    make_float2(0.5f * (p0 + p1), 0.5f * (p2 + p3));
            }
        }
    }
    __syncthreads();
    if (wid == 4) {
        asm volatile("tcgen05.dealloc.cta_group::1.sync.aligned.b32 %0, %1;"
                     :: "r"(tmem), "r"(128));
    }

#else  // ---------------- fallback: proven round-5 SIMT f32x2 GEMM ----------
#define FBK 8
    __shared__ float As[2][FBK][BM + 4];
    __shared__ float Bs[2][FBK][BN];

    const int tid = threadIdx.x;
    const int bi  = blockIdx.x;
    const int bm  = (bi / (NCOLS / BN)) * BM;
    const int bn  = (bi % (NCOLS / BN)) * BN;

    const int tx  = tid & 15;
    const int ty  = tid >> 4;
    const int tx4 = tx * 4;
    const int ty4 = ty * 4;

    const int arow  = tid >> 1;
    const int akoff = (tid & 1) * 4;
    const int brow  = tid >> 5;
    const int bcol  = (tid & 31) * 4;

    const float* gA = x + (size_t)(bm + arow) * HID + akoff;
    const float* gB = g_dW + (size_t)brow * NCOLS + bn + bcol;

    unsigned long long acc[8][4];
#pragma unroll
    for (int i = 0; i < 8; i++)
#pragma unroll
        for (int j = 0; j < 4; j++) acc[i][j] = 0ull;

    float4 fa = *(const float4*)(gA);
    float4 fb = *(const float4*)(gB);
    As[0][akoff + 0][arow] = fa.x;
    As[0][akoff + 1][arow] = fa.y;
    As[0][akoff + 2][arow] = fa.z;
    As[0][akoff + 3][arow] = fa.w;
    *(float4*)&Bs[0][brow][bcol] = fb;
    __syncthreads();

    const int KT = HID / FBK;
    int cur = 0;
    for (int t = 0; t < KT; ++t) {
        if (t + 1 < KT) {
            fa = *(const float4*)(gA + (t + 1) * FBK);
            fb = *(const float4*)(gB + (size_t)(t + 1) * FBK * NCOLS);
        }
#pragma unroll
        for (int k = 0; k < FBK; k++) {
            float4 a0 = *(const float4*)&As[cur][k][ty4];
            float4 a1 = *(const float4*)&As[cur][k][ty4 + 64];
            ulonglong2 b0 = *(const ulonglong2*)&Bs[cur][k][tx4];
            ulonglong2 b1 = *(const ulonglong2*)&Bs[cur][k][tx4 + 64];
            float av[8] = {a0.x, a0.y, a0.z, a0.w, a1.x, a1.y, a1.z, a1.w};
#pragma unroll
            for (int i = 0; i < 8; i++) {
                unsigned long long ap = pack2(av[i], av[i]);
                fma2(acc[i][0], ap, b0.x);
                fma2(acc[i][1], ap, b0.y);
                fma2(acc[i][2], ap, b1.x);
                fma2(acc[i][3], ap, b1.y);
            }
        }
        int nxt = cur ^ 1;
        if (t + 1 < KT) {
            As[nxt][akoff + 0][arow] = fa.x;
            As[nxt][akoff + 1][arow] = fa.y;
            As[nxt][akoff + 2][arow] = fa.z;
            As[nxt][akoff + 3][arow] = fa.w;
            *(float4*)&Bs[nxt][brow][bcol] = fb;
        }
        __syncthreads();
        cur = nxt;
    }

    float db[8];
#pragma unroll
    for (int j = 0; j < 8; j++) {
        int n = bn + tx4 + ((j >> 2) * 64) + (j & 3);
        db[j] = bias[2 * n] - bias[2 * n + 1];
    }
    const int gbase = (bn >> 1) + tx4 / 2;

#pragma unroll
    for (int i = 0; i < 8; i++) {
        int m = bm + ty4 + (i & 3) + ((i >> 2) * 64);
        const float* up = u + (size_t)m * (2 * NCOLS);
        int off0 = 2 * (bn + tx4);
        int off1 = 2 * (bn + tx4 + 64);
        float4 ua0 = *(const float4*)(up + off0);
        float4 ua1 = *(const float4*)(up + off0 + 4);
        float4 ub0 = *(const float4*)(up + off1);
        float4 ub1 = *(const float4*)(up + off1 + 4);
        float uv[16] = {ua0.x, ua0.y, ua0.z, ua0.w, ua1.x, ua1.y, ua1.z, ua1.w,
                        ub0.x, ub0.y, ub0.z, ub0.w, ub1.x, ub1.y, ub1.z, ub1.w};
        float2 d0 = unpack2(acc[i][0]);
        float2 d1 = unpack2(acc[i][1]);
        float2 d2 = unpack2(acc[i][2]);
        float2 d3 = unpack2(acc[i][3]);
        float dl[8] = {d0.x, d0.y, d1.x, d1.y, d2.x, d2.y, d3.x, d3.y};

        float p[8];
#pragma unroll
        for (int h = 0; h < 8; h++) {
            p[h] = sigp(dl[h] + db[h], uv[2 * h], uv[2 * h + 1]);
        }
        float* sc = g_scores + (size_t)m * NGROUPS;
        sc[gbase + 0]  = 0.5f * (p[0] + p[1]);
        sc[gbase + 1]  = 0.5f * (p[2] + p[3]);
        sc[gbase + 32] = 0.5f * (p[4] + p[5]);
        sc[gbase + 33] = 0.5f * (p[6] + p[7]);
    }
#endif  // TC_PATH
}

// ---------------------------------------------------------------------------
// Kernel C: top-budget selection with near-tie fp32 repair + output write.
// ---------------------------------------------------------------------------
__global__ __launch_bounds__(NGROUPS)
void rank_out_kernel(const float* __restrict__ latency,
                     const float* __restrict__ x,
                     const float* __restrict__ bias,
                     const float* __restrict__ u,
                     float* __restrict__ out) {
    __shared__ float kf[NGROUPS];
    __shared__ int   wsum[NGROUPS / 32];
    __shared__ unsigned s_fix[NGROUPS];      // recomputed keys (suspects only)
    __shared__ int   s_list[96];
    __shared__ int   s_n;
    __shared__ float red0[NGROUPS / 32], red1[NGROUPS / 32];

    const int b = blockIdx.x;
    const int t = threadIdx.x;
    const int lane = t & 31, w = t >> 5;

    float units = rintf(latency[b] * 512.0f);
    units = fminf(fmaxf(units, 128.0f), 512.0f);
    const int budget = (int)units - 128;

    unsigned key = __float_as_uint(g_scores[(size_t)b * NGROUPS + t]);
    if (t == 0) s_n = 0;

    // ---- pass 0: binary-search cutoff on approximate keys
    unsigned T = 0u;
#pragma unroll
    for (int bit = 31; bit >= 0; --bit) {
        unsigned cand = T | (1u << bit);
        int c = __syncthreads_count(key >= cand);
        if (c >= budget) T = cand;
    }

    // ---- flag near-tie suspects
    int myidx = -1;
    if (budget > 0) {
        float fT = __uint_as_float(T);
        float fs = __uint_as_float(key);
        if (fabsf(fs - fT) <= MARGIN) {
            int i = atomicAdd(&s_n, 1);
            if (i < 96) { s_list[i] = t; myidx = i; }
        }
    }
    __syncthreads();
    const int nsusp = min(s_n, 96);

    if (nsusp > 0) {
        // ---- exact fp32 recompute of each suspect group's score
        const float* xr = x + (size_t)b * HID;
        for (int si = 0; si < nsusp; ++si) {
            const int g = s_list[si];
            const float* w0 = g_dWn + (size_t)(2 * g) * HID;
            const float* w1 = g_dWn + (size_t)(2 * g + 1) * HID;
            float a = 0.0f, c2 = 0.0f;
            for (int k = t; k < HID; k += NGROUPS) {
                float xv = xr[k];
                a  = fmaf(xv, w0[k], a);
                c2 = fmaf(xv, w1[k], c2);
            }
#pragma unroll
            for (int o = 16; o > 0; o >>= 1) {
                a  += __shfl_down_sync(0xFFFFFFFFu, a, o);
                c2 += __shfl_down_sync(0xFFFFFFFFu, c2, o);
            }
            if (lane == 0) { red0[w] = a; red1[w] = c2; }
            __syncthreads();
            if (t == 0) {
                float la = 0.0f, lb = 0.0f;
#pragma unroll
                for (int ww = 0; ww < NGROUPS / 32; ++ww) { la += red0[ww]; lb += red1[ww]; }
                int n0 = 2 * g, n1 = 2 * g + 1;
                la += bias[2 * n0] - bias[2 * n0 + 1];
                lb += bias[2 * n1] - bias[2 * n1 + 1];
                const float* up = u + (size_t)b * (2 * NCOLS);
                float p0 = sigp(la, up[2 * n0], up[2 * n0 + 1]);
                float p1 = sigp(lb, up[2 * n1], up[2 * n1 + 1]);
                s_fix[g] = __float_as_uint(0.5f * (p0 + p1));
            }
            __syncthreads();
        }
        if (myidx >= 0) key = s_fix[t];

        // ---- pass 1: redo selection on corrected keys
        T = 0u;
#pragma unroll
        for (int bit = 31; bit >= 0; --bit) {
            unsigned cand = T | (1u << bit);
            int c = __syncthreads_count(key >= cand);
            if (c >= budget) T = cand;
        }
    }

    const int cgt  = __syncthreads_count(key > T);
    const int need = budget - cgt;

    const bool eq = (key == T);
    unsigned ball = __ballot_sync(0xFFFFFFFFu, eq);
    if (lane == 0) wsum[w] = __popc(ball);
    __syncthreads();
    int pre = 0;
    for (int ww = 0; ww < w; ww++) pre += wsum[ww];
    const int rank_eq = pre + __popc(ball & ((1u << lane) - 1u));

    const bool keep = (key > T) || (eq && rank_eq < need);
    kf[t] = keep ? 1.0f : 0.0f;
    __syncthreads();

    float* ob = out + (size_t)b * 2048;
    for (int idx = t; idx < 2048; idx += NGROUPS) {
        int l = idx >> 6;
        int h = idx & 31;
        int r = (idx >> 5) & 1;
        float v;
        if (l < 8) {
            v = 1.0f;
        } else {
            float k = kf[(l - 8) * 16 + (h >> 1)];
            v = r ? (1.0f - k) : k;
        }
        ob[idx] = v;
    }
}

// ---------------------------------------------------------------------------
extern "C" void kernel_launch(void* const* d_in, const int* in_sizes, int n_in,
                              void* d_out, int out_size) {
    const float* x       = (const float*)d_in[0];
    const float* latency = (const float*)d_in[1];
    const float* W       = (const float*)d_in[2];
    const float* bias    = (const float*)d_in[3];
    const float* u       = (const float*)d_in[4];
    float* out = (float*)d_out;

    // Which variant did the selected binary get? tcgen05 variant has ~0.6KB
    // static smem; SIMT fallback has ~16.5KB. Pick dynamic-smem request to match.
    size_t dyn = 0;
    cudaFuncAttributes fa;
    if (cudaFuncGetAttributes(&fa, gemm_score_kernel) == cudaSuccess &&
        fa.sharedSizeBytes < 8192) {
        cudaFuncSetAttribute(gemm_score_kernel,
                             cudaFuncAttributeMaxDynamicSharedMemorySize, DSMEM_BYTES);
        dyn = DSMEM_BYTES;
    }

    prep_dw_kernel<<<(HID * NCOLS + 255) / 256, 256>>>(W);
    gemm_score_kernel<<<(NB / BM) * (NCOLS / BN), 256, dyn>>>(x, bias, u);
    rank_out_kernel<<<NB, NGROUPS>>>(latency, x, bias, u, out);
}

// round 13
// speedup vs baseline: 1.9651x; 1.9651x over previous
#include <cuda_runtime.h>
#include <cstdint>

// Shapes: x:(16384,4096) f32, latency:(16384) f32, W:(4096,1536) f32,
// b:(1536) f32, u:(16384,24,32,2) f32  -> out:(16384,32,2,32) f32
#define NB      16384
#define HID     4096
#define NCOLS   768
#define NGROUPS 384
#define MARGIN  2.5e-4f

// tcgen05 path config
#define BM 128
#define BN 128
#define KC 32                  // fp32 elems per K-chunk (128B rows, SW128)
#define NCHUNK (HID / KC)      // 128
#define STAGES 3
#define STAGE_BYTES 32768      // A(tf32) 16K | B(tf32) 16K
#define DSMEM_BYTES (STAGES * STAGE_BYTES + 1024)   // 99328 -> 2 CTAs/SM
#define TC_THREADS 224
#define FB_THREADS 256

// Device-pass feature gate: tcgen05 exists only in arch-specific sm_10xa passes.
#if defined(__CUDA_ARCH_FEAT_SM103_ALL) || defined(__CUDA_ARCH_FEAT_SM100_ALL) || \
    defined(__CUDA_ARCH_FEAT_SM101_ALL)
#define TC_PATH 1
#endif

__device__ float g_Bt [(size_t)NCOLS * HID];   // dW tf32-rounded, [n][k] (TC GEMM B)
__device__ float g_dWn[(size_t)NCOLS * HID];   // dW exact fp32,   [n][k] (repair)
__device__ float g_dW [(size_t)HID * NCOLS];   // dW exact fp32,   [k][n] (fallback)
__device__ float g_scores[(size_t)NB * NGROUPS];

// ---------------------------------------------------------------- helpers
__device__ __forceinline__ uint32_t tf32_rna(float x) {
    uint32_t r; asm("cvt.rna.tf32.f32 %0, %1;" : "=r"(r) : "f"(x)); return r;
}
__device__ __forceinline__ unsigned long long pack2(float lo, float hi) {
    unsigned long long r;
    asm("mov.b64 %0, {%1, %2};" : "=l"(r) : "f"(lo), "f"(hi));
    return r;
}
__device__ __forceinline__ void fma2(unsigned long long& d,
                                     unsigned long long a, unsigned long long b) {
    asm("fma.rn.f32x2 %0, %1, %2, %0;" : "+l"(d) : "l"(a), "l"(b));
}
__device__ __forceinline__ float2 unpack2(unsigned long long v) {
    float2 r;
    asm("mov.b64 {%0, %1}, %2;" : "=f"(r.x), "=f"(r.y) : "l"(v));
    return r;
}
__device__ __forceinline__ float gum(float v) {
    float t = v * (1.0f - 2e-6f) + 1e-6f;
    return -logf(-logf(t));
}
__device__ __forceinline__ float sigp(float dl, float u0, float u1) {
    float z = (dl + gum(u0) - gum(u1)) * 0.2f;
    return 1.0f / (1.0f + __expf(-z));
}

#ifdef TC_PATH
__device__ __forceinline__ uint32_t smem_u32(const void* p) {
    uint32_t a;
    asm("{ .reg .u64 t; cvta.to.shared.u64 t, %1; cvt.u32.u64 %0, t; }"
        : "=r"(a) : "l"(p));
    return a;
}
__device__ __forceinline__ uint32_t elect1() {
    uint32_t p;
    asm volatile("{\n\t.reg .pred p;\n\telect.sync _|p, 0xFFFFFFFF;\n\t"
                 "selp.b32 %0, 1, 0, p;\n\t}" : "=r"(p));
    return p;
}
#define SW(o) ((uint32_t)(o) ^ ((((uint32_t)(o)) >> 3) & 0x70u))
#define MBAR_INIT(a, c) \
    asm volatile("mbarrier.init.shared.b64 [%0], %1;" :: "r"(a), "r"(c) : "memory")
#define MBAR_ARRIVE(a) \
    asm volatile("mbarrier.arrive.shared.b64 _, [%0];" :: "r"(a) : "memory")
__device__ __forceinline__ void mbar_wait(uint32_t a, uint32_t ph) {
    asm volatile(
        "{\n\t.reg .pred P;\n\t"
        "WL_%=:\n\t"
        "mbarrier.try_wait.parity.acquire.cta.shared::cta.b64 P, [%0], %1, 0x989680;\n\t"
        "@P bra.uni WD_%=;\n\t"
        "bra.uni WL_%=;\n\t"
        "WD_%=:\n\t}"
        :: "r"(a), "r"(ph) : "memory");
}
#define FENCE_ASYNC() asm volatile("fence.proxy.async.shared::cta;" ::: "memory")
#define NBAR(id, n) asm volatile("bar.sync %0, %1;" :: "r"(id), "r"(n) : "memory")
#define TC_COMMIT(a) \
    asm volatile("tcgen05.commit.cta_group::1.mbarrier::arrive::one.shared::cluster.b64 [%0];" \
                 :: "r"(a) : "memory")
#define TC_WAIT_LD() asm volatile("tcgen05.wait::ld.sync.aligned;" ::: "memory")

static constexpr unsigned long long DESC_BASE =
    (2ull << 61) | (1ull << 46) | (64ull << 32) | (1ull << 16);  // SW128 K-major
__device__ __forceinline__ uint64_t mk_desc(uint32_t addr) {
    return DESC_BASE | ((addr >> 4) & 0x3FFFull);
}
// SS tf32 MMA, cta_group::1. idesc: c=f32, a=b=tf32, M=128, N=64.
__device__ __forceinline__ void mma_tf32(uint32_t d, uint64_t a, uint64_t b,
                                         uint32_t idesc, uint32_t en) {
    asm volatile(
        "{\n\t.reg .pred p;\n\tsetp.ne.u32 p, %4, 0;\n\t"
        "tcgen05.mma.cta_group::1.kind::tf32 [%0], %1, %2, %3, {%5,%5,%5,%5}, p;\n\t}"
        :: "r"(d), "l"(a), "l"(b), "r"(idesc), "r"(en), "r"(0u) : "memory");
}
#define LDTM32(r, addr) \
    asm volatile( \
        "tcgen05.ld.sync.aligned.32x32b.x32.b32 " \
        "{%0, %1, %2, %3, %4, %5, %6, %7, " \
        " %8, %9, %10, %11, %12, %13, %14, %15, " \
        " %16, %17, %18, %19, %20, %21, %22, %23, " \
        " %24, %25, %26, %27, %28, %29, %30, %31}, [%32];" \
        : "=r"((r)[0]),  "=r"((r)[1]),  "=r"((r)[2]),  "=r"((r)[3]), \
          "=r"((r)[4]),  "=r"((r)[5]),  "=r"((r)[6]),  "=r"((r)[7]), \
          "=r"((r)[8]),  "=r"((r)[9]),  "=r"((r)[10]), "=r"((r)[11]), \
          "=r"((r)[12]), "=r"((r)[13]), "=r"((r)[14]), "=r"((r)[15]), \
          "=r"((r)[16]), "=r"((r)[17]), "=r"((r)[18]), "=r"((r)[19]), \
          "=r"((r)[20]), "=r"((r)[21]), "=r"((r)[22]), "=r"((r)[23]), \
          "=r"((r)[24]), "=r"((r)[25]), "=r"((r)[26]), "=r"((r)[27]), \
          "=r"((r)[28]), "=r"((r)[29]), "=r"((r)[30]), "=r"((r)[31]) \
        : "r"(addr))
#endif  // TC_PATH

// ---------------------------------------------------------------------------
// Kernel A: dW = W[:,even]-W[:,odd]; tf32 [n][k], exact [n][k] and [k][n].
// ---------------------------------------------------------------------------
__global__ void prep_dw_kernel(const float* __restrict__ W) {
    size_t idx = (size_t)blockIdx.x * 256 + threadIdx.x;
    if (idx >= (size_t)HID * NCOLS) return;
    int k = (int)(idx / NCOLS);
    int n = (int)(idx - (size_t)k * NCOLS);
    const float* wr = W + (size_t)k * (2 * NCOLS) + 2 * n;
    float d = wr[0] - wr[1];
    g_dW[idx] = d;                                    // [k][n], coalesced
    size_t tn = (size_t)n * HID + k;                  // [n][k]
    g_dWn[tn] = d;
    g_Bt[tn] = __uint_as_float(tf32_rna(d));
}

// ---------------------------------------------------------------------------
// Kernel B: GEMM + fused gumbel/sigmoid/pair-mean epilogue -> g_scores.
//   TC_PATH:  warp-specialized single-pass tcgen05 tf32 (RNA-rounded inputs)
//   fallback: proven SIMT f32x2 GEMM (round-5)
// ---------------------------------------------------------------------------
__global__ void
#ifdef TC_PATH
__launch_bounds__(TC_THREADS, 2)
#else
__launch_bounds__(FB_THREADS, 2)
#endif
gemm_score_kernel(const float* __restrict__ x,
                  const float* __restrict__ bias,
                  const float* __restrict__ u) {
#ifdef TC_PATH
    extern __shared__ char dsm_raw[];
    char* dbase = (char*)((((uintptr_t)dsm_raw) + 1023) & ~(uintptr_t)1023);
    const uint32_t dyn = smem_u32(dbase);

    __shared__ uint32_t s_tmem;
    __shared__ __align__(8) unsigned long long s_mbar[10];
    __shared__ float s_db[BN];

    const int tid = threadIdx.x;
    const int wid = tid >> 5;
    const int bi  = blockIdx.x;
    const int bm  = (bi / (NCOLS / BN)) * BM;
    const int bn  = (bi % (NCOLS / BN)) * BN;
    const uint32_t mb0 = smem_u32(s_mbar);
    // mbars: [0..2]=a_full(1) [3..5]=b_full(1) [6..8]=done(1) [9]=final(1)

    if (tid == 0) {
        for (int s = 0; s < STAGES; s++) {
            MBAR_INIT(mb0 + 8 * s, 1);
            MBAR_INIT(mb0 + 8 * (STAGES + s), 1);
            MBAR_INIT(mb0 + 8 * (2 * STAGES + s), 1);
        }
        MBAR_INIT(mb0 + 8 * 9, 1);
    }
    if (wid == 4) {
        asm volatile("tcgen05.alloc.cta_group::1.sync.aligned.shared::cta.b32 [%0], %1;"
                     :: "r"(smem_u32(&s_tmem)), "r"(128) : "memory");
        asm volatile("tcgen05.relinquish_alloc_permit.cta_group::1.sync.aligned;");
    }
    if (tid < BN) {
        int n = bn + tid;
        s_db[tid] = bias[2 * n] - bias[2 * n + 1];
    }
    __syncthreads();
    const uint32_t tmem = s_tmem;

    if (tid < 128) {
        // ---- A producer: 128 threads, x tile 128 rows x 32 cols, RNA->tf32
        const int kq = tid & 7;
        const int r0 = tid >> 3;
        int st = 0, ph = 1;
        for (int c = 0; c < NCHUNK; c++) {
            mbar_wait(mb0 + 8 * (2 * STAGES + st), ph);   // stage free
            char* as = dbase + st * STAGE_BYTES;
            const int k0 = c * KC;
#pragma unroll
            for (int p = 0; p < 8; p++) {
                int row = p * 16 + r0;
                float4 v = *(const float4*)(x + (size_t)(bm + row) * HID + k0 + kq * 4);
                uint32_t h0 = tf32_rna(v.x), h1 = tf32_rna(v.y);
                uint32_t h2 = tf32_rna(v.z), h3 = tf32_rna(v.w);
                uint32_t sw = SW(row * 128 + kq * 16);
                *(uint4*)(as + sw) = make_uint4(h0, h1, h2, h3);
            }
            NBAR(1, 128);
            if (tid == 0) {
                FENCE_ASYNC();
                MBAR_ARRIVE(mb0 + 8 * st);                // a_full
            }
            if (++st == STAGES) { st = 0; ph ^= 1; }
        }
    } else if (wid == 4) {
        // ---- MMA warp: 4 K-steps x 2 N-halves per chunk, split accumulators
        const uint32_t IDESC64 = 0x8100910u;  // f32 acc, tf32 a/b, M=128, N=64
        const uint32_t leader = elect1();
        int st = 0, ph = 0;
        for (int c = 0; c < NCHUNK; c++) {
            mbar_wait(mb0 + 8 * st, ph);                  // a_full
            mbar_wait(mb0 + 8 * (STAGES + st), ph);       // b_full
            if (leader) {
                uint32_t base = dyn + st * STAGE_BYTES;
                uint64_t ad = mk_desc(base);
                uint64_t bd = mk_desc(base + 16384);
#pragma unroll
                for (int j = 0; j < 4; j++) {             // K=8 per MMA
                    uint64_t o = 2 * j;
                    uint32_t en = !(c == 0 && j == 0);
                    mma_tf32(tmem,      ad + o, bd + o,       IDESC64, en);
                    mma_tf32(tmem + 64, ad + o, bd + o + 512, IDESC64, en);
                }
                TC_COMMIT(mb0 + 8 * (2 * STAGES + st));   // done -> stage reusable
            }
            if (++st == STAGES) { st = 0; ph ^= 1; }
        }
        if (leader) TC_COMMIT(mb0 + 8 * 9);               // final
    } else {
        // ---- B producer: 64 threads (warps 5-6), tf32-prerounded g_Bt
        const int t = tid - 160;
        int st = 0, ph = 1;
        for (int c = 0; c < NCHUNK; c++) {
            mbar_wait(mb0 + 8 * (2 * STAGES + st), ph);
            char* bs = dbase + st * STAGE_BYTES + 16384;
            const int k0 = c * KC;
#pragma unroll
            for (int i = 0; i < 16; i++) {
                int unit = t + 64 * i;                    // 0..1023
                int row = unit >> 3;
                int cu  = unit & 7;
                float4 v = *(const float4*)(g_Bt + (size_t)(bn + row) * HID + k0 + cu * 4);
                uint32_t sw = SW(row * 128 + cu * 16);
                *(float4*)(bs + sw) = v;
            }
            NBAR(2, 64);
            if (t == 0) {
                FENCE_ASYNC();
                MBAR_ARRIVE(mb0 + 8 * (STAGES + st));     // b_full
            }
            if (++st == STAGES) { st = 0; ph ^= 1; }
        }
    }

    __syncthreads();
    mbar_wait(mb0 + 8 * 9, 0);
    asm volatile("tcgen05.fence::after_thread_sync;" ::: "memory");

    if (wid < 4) {
        // ---- epilogue: thread owns row m = bm + tid (its warp subpartition)
        const int m = bm + tid;
        const float* up = u + (size_t)m * (2 * NCOLS) + 2 * bn;
        float* sp = g_scores + (size_t)m * NGROUPS + (bn >> 1);
#pragma unroll
        for (int cb = 0; cb < BN; cb += 32) {
            uint32_t d[32];
            LDTM32(d, tmem + cb);
            TC_WAIT_LD();
#pragma unroll
            for (int q = 0; q < 8; q++) {
                float4 u0 = *(const float4*)(up + 2 * cb + 8 * q);
                float4 u1 = *(const float4*)(up + 2 * cb + 8 * q + 4);
                int c0 = cb + 4 * q;
                float p0 = sigp(__uint_as_float(d[4 * q + 0]) + s_db[c0 + 0], u0.x, u0.y);
                float p1 = sigp(__uint_as_float(d[4 * q + 1]) + s_db[c0 + 1], u0.z, u0.w);
                float p2 = sigp(__uint_as_float(d[4 * q + 2]) + s_db[c0 + 2], u1.x, u1.y);
                float p3 = sigp(__uint_as_float(d[4 * q + 3]) + s_db[c0 + 3], u1.z, u1.w);
                *(float2*)(sp + (cb >> 1) + 2 * q) =
                    make_float2(0.5f * (p0 + p1), 0.5f * (p2 + p3));
            }
        }
    }
    __syncthreads();
    if (wid == 4) {
        asm volatile("tcgen05.dealloc.cta_group::1.sync.aligned.b32 %0, %1;"
                     :: "r"(tmem), "r"(128));
    }

#else  // ---------------- fallback: proven round-5 SIMT f32x2 GEMM ----------
#define FBK 8
    __shared__ float As[2][FBK][BM + 4];
    __shared__ float Bs[2][FBK][BN];

    const int tid = threadIdx.x;
    const int bi  = blockIdx.x;
    const int bm  = (bi / (NCOLS / BN)) * BM;
    const int bn  = (bi % (NCOLS / BN)) * BN;

    const int tx  = tid & 15;
    const int ty  = tid >> 4;
    const int tx4 = tx * 4;
    const int ty4 = ty * 4;

    const int arow  = tid >> 1;
    const int akoff = (tid & 1) * 4;
    const int brow  = tid >> 5;
    const int bcol  = (tid & 31) * 4;

    const float* gA = x + (size_t)(bm + arow) * HID + akoff;
    const float* gB = g_dW + (size_t)brow * NCOLS + bn + bcol;

    unsigned long long acc[8][4];
#pragma unroll
    for (int i = 0; i < 8; i++)
#pragma unroll
        for (int j = 0; j < 4; j++) acc[i][j] = 0ull;

    float4 fa = *(const float4*)(gA);
    float4 fb = *(const float4*)(gB);
    As[0][akoff + 0][arow] = fa.x;
    As[0][akoff + 1][arow] = fa.y;
    As[0][akoff + 2][arow] = fa.z;
    As[0][akoff + 3][arow] = fa.w;
    *(float4*)&Bs[0][brow][bcol] = fb;
    __syncthreads();

    const int KT = HID / FBK;
    int cur = 0;
    for (int t = 0; t < KT; ++t) {
        if (t + 1 < KT) {
            fa = *(const float4*)(gA + (t + 1) * FBK);
            fb = *(const float4*)(gB + (size_t)(t + 1) * FBK * NCOLS);
        }
#pragma unroll
        for (int k = 0; k < FBK; k++) {
            float4 a0 = *(const float4*)&As[cur][k][ty4];
            float4 a1 = *(const float4*)&As[cur][k][ty4 + 64];
            ulonglong2 b0 = *(const ulonglong2*)&Bs[cur][k][tx4];
            ulonglong2 b1 = *(const ulonglong2*)&Bs[cur][k][tx4 + 64];
            float av[8] = {a0.x, a0.y, a0.z, a0.w, a1.x, a1.y, a1.z, a1.w};
#pragma unroll
            for (int i = 0; i < 8; i++) {
                unsigned long long ap = pack2(av[i], av[i]);
                fma2(acc[i][0], ap, b0.x);
                fma2(acc[i][1], ap, b0.y);
                fma2(acc[i][2], ap, b1.x);
                fma2(acc[i][3], ap, b1.y);
            }
        }
        int nxt = cur ^ 1;
        if (t + 1 < KT) {
            As[nxt][akoff + 0][arow] = fa.x;
            As[nxt][akoff + 1][arow] = fa.y;
            As[nxt][akoff + 2][arow] = fa.z;
            As[nxt][akoff + 3][arow] = fa.w;
            *(float4*)&Bs[nxt][brow][bcol] = fb;
        }
        __syncthreads();
        cur = nxt;
    }

    float db[8];
#pragma unroll
    for (int j = 0; j < 8; j++) {
        int n = bn + tx4 + ((j >> 2) * 64) + (j & 3);
        db[j] = bias[2 * n] - bias[2 * n + 1];
    }
    const int gbase = (bn >> 1) + tx4 / 2;

#pragma unroll
    for (int i = 0; i < 8; i++) {
        int m = bm + ty4 + (i & 3) + ((i >> 2) * 64);
        const float* up = u + (size_t)m * (2 * NCOLS);
        int off0 = 2 * (bn + tx4);
        int off1 = 2 * (bn + tx4 + 64);
        float4 ua0 = *(const float4*)(up + off0);
        float4 ua1 = *(const float4*)(up + off0 + 4);
        float4 ub0 = *(const float4*)(up + off1);
        float4 ub1 = *(const float4*)(up + off1 + 4);
        float uv[16] = {ua0.x, ua0.y, ua0.z, ua0.w, ua1.x, ua1.y, ua1.z, ua1.w,
                        ub0.x, ub0.y, ub0.z, ub0.w, ub1.x, ub1.y, ub1.z, ub1.w};
        float2 d0 = unpack2(acc[i][0]);
        float2 d1 = unpack2(acc[i][1]);
        float2 d2 = unpack2(acc[i][2]);
        float2 d3 = unpack2(acc[i][3]);
        float dl[8] = {d0.x, d0.y, d1.x, d1.y, d2.x, d2.y, d3.x, d3.y};

        float p[8];
#pragma unroll
        for (int h = 0; h < 8; h++) {
            p[h] = sigp(dl[h] + db[h], uv[2 * h], uv[2 * h + 1]);
        }
        float* sc = g_scores + (size_t)m * NGROUPS;
        sc[gbase + 0]  = 0.5f * (p[0] + p[1]);
        sc[gbase + 1]  = 0.5f * (p[2] + p[3]);
        sc[gbase + 32] = 0.5f * (p[4] + p[5]);
        sc[gbase + 33] = 0.5f * (p[6] + p[7]);
    }
#endif  // TC_PATH
}

// ---------------------------------------------------------------------------
// Kernel C: top-budget selection with near-tie fp32 repair + output write.
// ---------------------------------------------------------------------------
__global__ __launch_bounds__(NGROUPS)
void rank_out_kernel(const float* __restrict__ latency,
                     const float* __restrict__ x,
                     const float* __restrict__ bias,
                     const float* __restrict__ u,
                     float* __restrict__ out) {
    __shared__ float kf[NGROUPS];
    __shared__ int   wsum[NGROUPS / 32];
    __shared__ unsigned s_fix[NGROUPS];      // recomputed keys (suspects only)
    __shared__ int   s_list[64];
    __shared__ int   s_n;
    __shared__ float red0[NGROUPS / 32], red1[NGROUPS / 32];

    const int b = blockIdx.x;
    const int t = threadIdx.x;
    const int lane = t & 31, w = t >> 5;

    float units = rintf(latency[b] * 512.0f);
    units = fminf(fmaxf(units, 128.0f), 512.0f);
    const int budget = (int)units - 128;

    unsigned key = __float_as_uint(g_scores[(size_t)b * NGROUPS + t]);
    if (t == 0) s_n = 0;

    // ---- pass 0: binary-search cutoff on approximate keys
    unsigned T = 0u;
#pragma unroll
    for (int bit = 31; bit >= 0; --bit) {
        unsigned cand = T | (1u << bit);
        int c = __syncthreads_count(key >= cand);
        if (c >= budget) T = cand;
    }

    // ---- flag near-tie suspects
    int myidx = -1;
    if (budget > 0) {
        float fT = __uint_as_float(T);
        float fs = __uint_as_float(key);
        if (fabsf(fs - fT) <= MARGIN) {
            int i = atomicAdd(&s_n, 1);
            if (i < 64) { s_list[i] = t; myidx = i; }
        }
    }
    __syncthreads();
    const int nsusp = min(s_n, 64);

    if (nsusp > 0) {
        // ---- exact fp32 recompute of each suspect group's score
        const float* xr = x + (size_t)b * HID;
        for (int si = 0; si < nsusp; ++si) {
            const int g = s_list[si];
            const float* w0 = g_dWn + (size_t)(2 * g) * HID;
            const float* w1 = g_dWn + (size_t)(2 * g + 1) * HID;
            float a = 0.0f, c2 = 0.0f;
            for (int k = t; k < HID; k += NGROUPS) {
                float xv = xr[k];
                a  = fmaf(xv, w0[k], a);
                c2 = fmaf(xv, w1[k], c2);
            }
#pragma unroll
            for (int o = 16; o > 0; o >>= 1) {
                a  += __shfl_down_sync(0xFFFFFFFFu, a, o);
                c2 += __shfl_down_sync(0xFFFFFFFFu, c2, o);
            }
            if (lane == 0) { red0[w] = a; red1[w] = c2; }
            __syncthreads();
            if (t == 0) {
                float la = 0.0f, lb = 0.0f;
#pragma unroll
                for (int ww = 0; ww < NGROUPS / 32; ++ww) { la += red0[ww]; lb += red1[ww]; }
                int n0 = 2 * g, n1 = 2 * g + 1;
                la += bias[2 * n0] - bias[2 * n0 + 1];
                lb += bias[2 * n1] - bias[2 * n1 + 1];
                const float* up = u + (size_t)b * (2 * NCOLS);
                float p0 = sigp(la, up[2 * n0], up[2 * n0 + 1]);
                float p1 = sigp(lb, up[2 * n1], up[2 * n1 + 1]);
                s_fix[g] = __float_as_uint(0.5f * (p0 + p1));
            }
            __syncthreads();
        }
        if (myidx >= 0) key = s_fix[t];

        // ---- pass 1: redo selection on corrected keys
        T = 0u;
#pragma unroll
        for (int bit = 31; bit >= 0; --bit) {
            unsigned cand = T | (1u << bit);
            int c = __syncthreads_count(key >= cand);
            if (c >= budget) T = cand;
        }
    }

    const int cgt  = __syncthreads_count(key > T);
    const int need = budget - cgt;

    const bool eq = (key == T);
    unsigned ball = __ballot_sync(0xFFFFFFFFu, eq);
    if (lane == 0) wsum[w] = __popc(ball);
    __syncthreads();
    int pre = 0;
    for (int ww = 0; ww < w; ww++) pre += wsum[ww];
    const int rank_eq = pre + __popc(ball & ((1u << lane) - 1u));

    const bool keep = (key > T) || (eq && rank_eq < need);
    kf[t] = keep ? 1.0f : 0.0f;
    __syncthreads();

    float* ob = out + (size_t)b * 2048;
    for (int idx = t; idx < 2048; idx += NGROUPS) {
        int l = idx >> 6;
        int h = idx & 31;
        int r = (idx >> 5) & 1;
        float v;
        if (l < 8) {
            v = 1.0f;
        } else {
            float k = kf[(l - 8) * 16 + (h >> 1)];
            v = r ? (1.0f - k) : k;
        }
        ob[idx] = v;
    }
}

// ---------------------------------------------------------------------------
extern "C" void kernel_launch(void* const* d_in, const int* in_sizes, int n_in,
                              void* d_out, int out_size) {
    const float* x       = (const float*)d_in[0];
    const float* latency = (const float*)d_in[1];
    const float* W       = (const float*)d_in[2];
    const float* bias    = (const float*)d_in[3];
    const float* u       = (const float*)d_in[4];
    float* out = (float*)d_out;

    // Variant sniff: tcgen05 build has ~0.8KB static smem; SIMT fallback ~16.6KB.
    size_t dyn = 0;
    int threads = FB_THREADS;
    cudaFuncAttributes fa;
    if (cudaFuncGetAttributes(&fa, gemm_score_kernel) == cudaSuccess &&
        fa.sharedSizeBytes < 8192) {
        cudaFuncSetAttribute(gemm_score_kernel,
                             cudaFuncAttributeMaxDynamicSharedMemorySize, DSMEM_BYTES);
        dyn = DSMEM_BYTES;
        threads = TC_THREADS;
    }

    prep_dw_kernel<<<(HID * NCOLS + 255) / 256, 256>>>(W);
    gemm_score_kernel<<<(NB / BM) * (NCOLS / BN), threads, dyn>>>(x, bias, u);
    rank_out_kernel<<<NB, NGROUPS>>>(latency, x, bias, u, out);
}

// round 14
// speedup vs baseline: 6.4091x; 3.2615x over previous
#include <cuda_runtime.h>
#include <cstdint>

// Shapes: x:(16384,4096) f32, latency:(16384) f32, W:(4096,1536) f32,
// b:(1536) f32, u:(16384,24,32,2) f32  -> out:(16384,32,2,32) f32
#define NB      16384
#define HID     4096
#define NCOLS   768
#define NGROUPS 384
#define MARGIN  2.5e-4f

// tcgen05 path config
#define BM 128
#define BN 128
#define KC 32                  // fp32 elems per K-chunk (128B rows, SW128)
#define NCHUNK (HID / KC)      // 128
#define STAGES 3
#define STAGE_BYTES 32768      // A(tf32) 16K | B(tf32) 16K
#define DSMEM_BYTES (STAGES * STAGE_BYTES + 1024)   // 99328 -> 2 CTAs/SM
#define TC_THREADS 224
#define FB_THREADS 256

// Device-pass feature gate: tcgen05 exists only in arch-specific sm_10xa passes.
#if defined(__CUDA_ARCH_FEAT_SM103_ALL) || defined(__CUDA_ARCH_FEAT_SM100_ALL) || \
    defined(__CUDA_ARCH_FEAT_SM101_ALL)
#define TC_PATH 1
#endif

__device__ float g_Bt [(size_t)NCOLS * HID];   // dW tf32-rounded, [n][k] (TC GEMM B)
__device__ float g_dWn[(size_t)NCOLS * HID];   // dW exact fp32,   [n][k] (repair)
__device__ float g_dW [(size_t)HID * NCOLS];   // dW exact fp32,   [k][n] (fallback)
__device__ float g_scores[(size_t)NB * NGROUPS];

// ---------------------------------------------------------------- helpers
__device__ __forceinline__ uint32_t tf32_rna(float x) {
    uint32_t r; asm("cvt.rna.tf32.f32 %0, %1;" : "=r"(r) : "f"(x)); return r;
}
__device__ __forceinline__ unsigned long long pack2(float lo, float hi) {
    unsigned long long r;
    asm("mov.b64 %0, {%1, %2};" : "=l"(r) : "f"(lo), "f"(hi));
    return r;
}
__device__ __forceinline__ void fma2(unsigned long long& d,
                                     unsigned long long a, unsigned long long b) {
    asm("fma.rn.f32x2 %0, %1, %2, %0;" : "+l"(d) : "l"(a), "l"(b));
}
__device__ __forceinline__ float2 unpack2(unsigned long long v) {
    float2 r;
    asm("mov.b64 {%0, %1}, %2;" : "=f"(r.x), "=f"(r.y) : "l"(v));
    return r;
}
__device__ __forceinline__ float gum(float v) {
    float t = v * (1.0f - 2e-6f) + 1e-6f;
    return -logf(-logf(t));
}
__device__ __forceinline__ float sigp(float dl, float u0, float u1) {
    float z = (dl + gum(u0) - gum(u1)) * 0.2f;
    return 1.0f / (1.0f + __expf(-z));
}

#ifdef TC_PATH
__device__ __forceinline__ uint32_t smem_u32(const void* p) {
    uint32_t a;
    asm("{ .reg .u64 t; cvta.to.shared.u64 t, %1; cvt.u32.u64 %0, t; }"
        : "=r"(a) : "l"(p));
    return a;
}
__device__ __forceinline__ uint32_t elect1() {
    uint32_t p;
    asm volatile("{\n\t.reg .pred p;\n\telect.sync _|p, 0xFFFFFFFF;\n\t"
                 "selp.b32 %0, 1, 0, p;\n\t}" : "=r"(p));
    return p;
}
#define SW(o) ((uint32_t)(o) ^ ((((uint32_t)(o)) >> 3) & 0x70u))
#define MBAR_INIT(a, c) \
    asm volatile("mbarrier.init.shared.b64 [%0], %1;" :: "r"(a), "r"(c) : "memory")
#define MBAR_ARRIVE(a) \
    asm volatile("mbarrier.arrive.shared.b64 _, [%0];" :: "r"(a) : "memory")
__device__ __forceinline__ void mbar_wait(uint32_t a, uint32_t ph) {
    asm volatile(
        "{\n\t.reg .pred P;\n\t"
        "WL_%=:\n\t"
        "mbarrier.try_wait.parity.acquire.cta.shared::cta.b64 P, [%0], %1, 0x80;\n\t"
        "@P bra.uni WD_%=;\n\t"
        "bra.uni WL_%=;\n\t"
        "WD_%=:\n\t}"
        :: "r"(a), "r"(ph) : "memory");
}
#define FENCE_ASYNC() asm volatile("fence.proxy.async.shared::cta;" ::: "memory")
#define NBAR(id, n) asm volatile("bar.sync %0, %1;" :: "r"(id), "r"(n) : "memory")
#define TC_COMMIT(a) \
    asm volatile("tcgen05.commit.cta_group::1.mbarrier::arrive::one.shared::cluster.b64 [%0];" \
                 :: "r"(a) : "memory")
#define TC_WAIT_LD() asm volatile("tcgen05.wait::ld.sync.aligned;" ::: "memory")

static constexpr unsigned long long DESC_BASE =
    (2ull << 61) | (1ull << 46) | (64ull << 32) | (1ull << 16);  // SW128 K-major
__device__ __forceinline__ uint64_t mk_desc(uint32_t addr) {
    return DESC_BASE | ((addr >> 4) & 0x3FFFull);
}
// SS tf32 MMA, cta_group::1. idesc 0x8200910: c=f32, a=b=tf32, M=128, N=128.
__device__ __forceinline__ void mma_tf32(uint32_t d, uint64_t a, uint64_t b,
                                         uint32_t idesc, uint32_t en) {
    asm volatile(
        "{\n\t.reg .pred p;\n\tsetp.ne.u32 p, %4, 0;\n\t"
        "tcgen05.mma.cta_group::1.kind::tf32 [%0], %1, %2, %3, {%5,%5,%5,%5}, p;\n\t}"
        :: "r"(d), "l"(a), "l"(b), "r"(idesc), "r"(en), "r"(0u) : "memory");
}
#define LDTM32(r, addr) \
    asm volatile( \
        "tcgen05.ld.sync.aligned.32x32b.x32.b32 " \
        "{%0, %1, %2, %3, %4, %5, %6, %7, " \
        " %8, %9, %10, %11, %12, %13, %14, %15, " \
        " %16, %17, %18, %19, %20, %21, %22, %23, " \
        " %24, %25, %26, %27, %28, %29, %30, %31}, [%32];" \
        : "=r"((r)[0]),  "=r"((r)[1]),  "=r"((r)[2]),  "=r"((r)[3]), \
          "=r"((r)[4]),  "=r"((r)[5]),  "=r"((r)[6]),  "=r"((r)[7]), \
          "=r"((r)[8]),  "=r"((r)[9]),  "=r"((r)[10]), "=r"((r)[11]), \
          "=r"((r)[12]), "=r"((r)[13]), "=r"((r)[14]), "=r"((r)[15]), \
          "=r"((r)[16]), "=r"((r)[17]), "=r"((r)[18]), "=r"((r)[19]), \
          "=r"((r)[20]), "=r"((r)[21]), "=r"((r)[22]), "=r"((r)[23]), \
          "=r"((r)[24]), "=r"((r)[25]), "=r"((r)[26]), "=r"((r)[27]), \
          "=r"((r)[28]), "=r"((r)[29]), "=r"((r)[30]), "=r"((r)[31]) \
        : "r"(addr))
#endif  // TC_PATH

// ---------------------------------------------------------------------------
// Kernel A: dW = W[:,even]-W[:,odd]; tf32 [n][k], exact [n][k] and [k][n].
// ---------------------------------------------------------------------------
__global__ void prep_dw_kernel(const float* __restrict__ W) {
    size_t idx = (size_t)blockIdx.x * 256 + threadIdx.x;
    if (idx >= (size_t)HID * NCOLS) return;
    int k = (int)(idx / NCOLS);
    int n = (int)(idx - (size_t)k * NCOLS);
    const float* wr = W + (size_t)k * (2 * NCOLS) + 2 * n;
    float d = wr[0] - wr[1];
    g_dW[idx] = d;                                    // [k][n], coalesced
    size_t tn = (size_t)n * HID + k;                  // [n][k]
    g_dWn[tn] = d;
    g_Bt[tn] = __uint_as_float(tf32_rna(d));
}

// ---------------------------------------------------------------------------
// Kernel B: GEMM + fused gumbel/sigmoid/pair-mean epilogue -> g_scores.
//   TC_PATH:  warp-specialized single-pass tcgen05 tf32, prefetch-before-wait
//   fallback: proven SIMT f32x2 GEMM (round-5)
// ---------------------------------------------------------------------------
__global__ void
#ifdef TC_PATH
__launch_bounds__(TC_THREADS, 2)
#else
__launch_bounds__(FB_THREADS, 2)
#endif
gemm_score_kernel(const float* __restrict__ x,
                  const float* __restrict__ bias,
                  const float* __restrict__ u) {
#ifdef TC_PATH
    extern __shared__ char dsm_raw[];
    char* dbase = (char*)((((uintptr_t)dsm_raw) + 1023) & ~(uintptr_t)1023);
    const uint32_t dyn = smem_u32(dbase);

    __shared__ uint32_t s_tmem;
    __shared__ __align__(8) unsigned long long s_mbar[10];
    __shared__ float s_db[BN];

    const int tid = threadIdx.x;
    const int wid = tid >> 5;
    const int bi  = blockIdx.x;
    const int bm  = (bi / (NCOLS / BN)) * BM;
    const int bn  = (bi % (NCOLS / BN)) * BN;
    const uint32_t mb0 = smem_u32(s_mbar);
    // mbars: [0..2]=a_full(1) [3..5]=b_full(1) [6..8]=done(1) [9]=final(1)

    if (tid == 0) {
        for (int s = 0; s < STAGES; s++) {
            MBAR_INIT(mb0 + 8 * s, 1);
            MBAR_INIT(mb0 + 8 * (STAGES + s), 1);
            MBAR_INIT(mb0 + 8 * (2 * STAGES + s), 1);
        }
        MBAR_INIT(mb0 + 8 * 9, 1);
    }
    if (wid == 4) {
        asm volatile("tcgen05.alloc.cta_group::1.sync.aligned.shared::cta.b32 [%0], %1;"
                     :: "r"(smem_u32(&s_tmem)), "r"(128) : "memory");
        asm volatile("tcgen05.relinquish_alloc_permit.cta_group::1.sync.aligned;");
    }
    if (tid < BN) {
        int n = bn + tid;
        s_db[tid] = bias[2 * n] - bias[2 * n + 1];
    }
    __syncthreads();
    const uint32_t tmem = s_tmem;

    if (tid < 128) {
        // ---- A producer: prefetch LDGs into regs BEFORE stage-free wait.
        const int kq = tid & 7;
        const int r0 = tid >> 3;
        int st = 0, ph = 1;
        for (int c = 0; c < NCHUNK; c++) {
            const int k0 = c * KC;
            float4 v[8];
#pragma unroll
            for (int p = 0; p < 8; p++)
                v[p] = *(const float4*)(x + (size_t)(bm + p * 16 + r0) * HID + k0 + kq * 4);
            mbar_wait(mb0 + 8 * (2 * STAGES + st), ph);   // stage free
            char* as = dbase + st * STAGE_BYTES;
#pragma unroll
            for (int p = 0; p < 8; p++) {
                int row = p * 16 + r0;
                uint32_t h0 = tf32_rna(v[p].x), h1 = tf32_rna(v[p].y);
                uint32_t h2 = tf32_rna(v[p].z), h3 = tf32_rna(v[p].w);
                uint32_t sw = SW(row * 128 + kq * 16);
                *(uint4*)(as + sw) = make_uint4(h0, h1, h2, h3);
            }
            NBAR(1, 128);
            if (tid == 0) {
                FENCE_ASYNC();
                MBAR_ARRIVE(mb0 + 8 * st);                // a_full
            }
            if (++st == STAGES) { st = 0; ph ^= 1; }
        }
    } else if (wid == 4) {
        // ---- MMA warp: 4 K-steps per chunk at N=128, single accumulator
        const uint32_t IDESC = 0x8200910u;  // f32 acc, tf32 a/b, M=128, N=128
        const uint32_t leader = elect1();
        int st = 0, ph = 0;
        for (int c = 0; c < NCHUNK; c++) {
            mbar_wait(mb0 + 8 * st, ph);                  // a_full
            mbar_wait(mb0 + 8 * (STAGES + st), ph);       // b_full
            if (leader) {
                uint32_t base = dyn + st * STAGE_BYTES;
                uint64_t ad = mk_desc(base);
                uint64_t bd = mk_desc(base + 16384);
#pragma unroll
                for (int j = 0; j < 4; j++) {             // K=8 per MMA
                    uint64_t o = 2 * j;
                    mma_tf32(tmem, ad + o, bd + o, IDESC, !(c == 0 && j == 0));
                }
                TC_COMMIT(mb0 + 8 * (2 * STAGES + st));   // done -> stage reusable
            }
            if (++st == STAGES) { st = 0; ph ^= 1; }
        }
        if (leader) TC_COMMIT(mb0 + 8 * 9);               // final
    } else {
        // ---- B producer: 64 threads (warps 5-6), prefetch-before-wait
        const int t = tid - 160;
        int st = 0, ph = 1;
        for (int c = 0; c < NCHUNK; c++) {
            const int k0 = c * KC;
            float4 v[16];
#pragma unroll
            for (int i = 0; i < 16; i++) {
                int unit = t + 64 * i;                    // 0..1023
                int row = unit >> 3;
                int cu  = unit & 7;
                v[i] = *(const float4*)(g_Bt + (size_t)(bn + row) * HID + k0 + cu * 4);
            }
            mbar_wait(mb0 + 8 * (2 * STAGES + st), ph);
            char* bs = dbase + st * STAGE_BYTES + 16384;
#pragma unroll
            for (int i = 0; i < 16; i++) {
                int unit = t + 64 * i;
                int row = unit >> 3;
                int cu  = unit & 7;
                uint32_t sw = SW(row * 128 + cu * 16);
                *(float4*)(bs + sw) = v[i];
            }
            NBAR(2, 64);
            if (t == 0) {
                FENCE_ASYNC();
                MBAR_ARRIVE(mb0 + 8 * (STAGES + st));     // b_full
            }
            if (++st == STAGES) { st = 0; ph ^= 1; }
        }
    }

    __syncthreads();
    mbar_wait(mb0 + 8 * 9, 0);
    asm volatile("tcgen05.fence::after_thread_sync;" ::: "memory");

    if (wid < 4) {
        // ---- epilogue: thread owns row m = bm + tid (its warp subpartition)
        const int m = bm + tid;
        const float* up = u + (size_t)m * (2 * NCOLS) + 2 * bn;
        float* sp = g_scores + (size_t)m * NGROUPS + (bn >> 1);
#pragma unroll
        for (int cb = 0; cb < BN; cb += 32) {
            uint32_t d[32];
            LDTM32(d, tmem + cb);
            TC_WAIT_LD();
#pragma unroll
            for (int q = 0; q < 8; q++) {
                float4 u0 = *(const float4*)(up + 2 * cb + 8 * q);
                float4 u1 = *(const float4*)(up + 2 * cb + 8 * q + 4);
                int c0 = cb + 4 * q;
                float p0 = sigp(__uint_as_float(d[4 * q + 0]) + s_db[c0 + 0], u0.x, u0.y);
                float p1 = sigp(__uint_as_float(d[4 * q + 1]) + s_db[c0 + 1], u0.z, u0.w);
                float p2 = sigp(__uint_as_float(d[4 * q + 2]) + s_db[c0 + 2], u1.x, u1.y);
                float p3 = sigp(__uint_as_float(d[4 * q + 3]) + s_db[c0 + 3], u1.z, u1.w);
                *(float2*)(sp + (cb >> 1) + 2 * q) =
                    make_float2(0.5f * (p0 + p1), 0.5f * (p2 + p3));
            }
        }
    }
    __syncthreads();
    if (wid == 4) {
        asm volatile("tcgen05.dealloc.cta_group::1.sync.aligned.b32 %0, %1;"
                     :: "r"(tmem), "r"(128));
    }

#else  // ---------------- fallback: proven round-5 SIMT f32x2 GEMM ----------
#define FBK 8
    __shared__ float As[2][FBK][BM + 4];
    __shared__ float Bs[2][FBK][BN];

    const int tid = threadIdx.x;
    const int bi  = blockIdx.x;
    const int bm  = (bi / (NCOLS / BN)) * BM;
    const int bn  = (bi % (NCOLS / BN)) * BN;

    const int tx  = tid & 15;
    const int ty  = tid >> 4;
    const int tx4 = tx * 4;
    const int ty4 = ty * 4;

    const int arow  = tid >> 1;
    const int akoff = (tid & 1) * 4;
    const int brow  = tid >> 5;
    const int bcol  = (tid & 31) * 4;

    const float* gA = x + (size_t)(bm + arow) * HID + akoff;
    const float* gB = g_dW + (size_t)brow * NCOLS + bn + bcol;

    unsigned long long acc[8][4];
#pragma unroll
    for (int i = 0; i < 8; i++)
#pragma unroll
        for (int j = 0; j < 4; j++) acc[i][j] = 0ull;

    float4 fa = *(const float4*)(gA);
    float4 fb = *(const float4*)(gB);
    As[0][akoff + 0][arow] = fa.x;
    As[0][akoff + 1][arow] = fa.y;
    As[0][akoff + 2][arow] = fa.z;
    As[0][akoff + 3][arow] = fa.w;
    *(float4*)&Bs[0][brow][bcol] = fb;
    __syncthreads();

    const int KT = HID / FBK;
    int cur = 0;
    for (int t = 0; t < KT; ++t) {
        if (t + 1 < KT) {
            fa = *(const float4*)(gA + (t + 1) * FBK);
            fb = *(const float4*)(gB + (size_t)(t + 1) * FBK * NCOLS);
        }
#pragma unroll
        for (int k = 0; k < FBK; k++) {
            float4 a0 = *(const float4*)&As[cur][k][ty4];
            float4 a1 = *(const float4*)&As[cur][k][ty4 + 64];
            ulonglong2 b0 = *(const ulonglong2*)&Bs[cur][k][tx4];
            ulonglong2 b1 = *(const ulonglong2*)&Bs[cur][k][tx4 + 64];
            float av[8] = {a0.x, a0.y, a0.z, a0.w, a1.x, a1.y, a1.z, a1.w};
#pragma unroll
            for (int i = 0; i < 8; i++) {
                unsigned long long ap = pack2(av[i], av[i]);
                fma2(acc[i][0], ap, b0.x);
                fma2(acc[i][1], ap, b0.y);
                fma2(acc[i][2], ap, b1.x);
                fma2(acc[i][3], ap, b1.y);
            }
        }
        int nxt = cur ^ 1;
        if (t + 1 < KT) {
            As[nxt][akoff + 0][arow] = fa.x;
            As[nxt][akoff + 1][arow] = fa.y;
            As[nxt][akoff + 2][arow] = fa.z;
            As[nxt][akoff + 3][arow] = fa.w;
            *(float4*)&Bs[nxt][brow][bcol] = fb;
        }
        __syncthreads();
        cur = nxt;
    }

    float db[8];
#pragma unroll
    for (int j = 0; j < 8; j++) {
        int n = bn + tx4 + ((j >> 2) * 64) + (j & 3);
        db[j] = bias[2 * n] - bias[2 * n + 1];
    }
    const int gbase = (bn >> 1) + tx4 / 2;

#pragma unroll
    for (int i = 0; i < 8; i++) {
        int m = bm + ty4 + (i & 3) + ((i >> 2) * 64);
        const float* up = u + (size_t)m * (2 * NCOLS);
        int off0 = 2 * (bn + tx4);
        int off1 = 2 * (bn + tx4 + 64);
        float4 ua0 = *(const float4*)(up + off0);
        float4 ua1 = *(const float4*)(up + off0 + 4);
        float4 ub0 = *(const float4*)(up + off1);
        float4 ub1 = *(const float4*)(up + off1 + 4);
        float uv[16] = {ua0.x, ua0.y, ua0.z, ua0.w, ua1.x, ua1.y, ua1.z, ua1.w,
                        ub0.x, ub0.y, ub0.z, ub0.w, ub1.x, ub1.y, ub1.z, ub1.w};
        float2 d0 = unpack2(acc[i][0]);
        float2 d1 = unpack2(acc[i][1]);
        float2 d2 = unpack2(acc[i][2]);
        float2 d3 = unpack2(acc[i][3]);
        float dl[8] = {d0.x, d0.y, d1.x, d1.y, d2.x, d2.y, d3.x, d3.y};

        float p[8];
#pragma unroll
        for (int h = 0; h < 8; h++) {
            p[h] = sigp(dl[h] + db[h], uv[2 * h], uv[2 * h + 1]);
        }
        float* sc = g_scores + (size_t)m * NGROUPS;
        sc[gbase + 0]  = 0.5f * (p[0] + p[1]);
        sc[gbase + 1]  = 0.5f * (p[2] + p[3]);
        sc[gbase + 32] = 0.5f * (p[4] + p[5]);
        sc[gbase + 33] = 0.5f * (p[6] + p[7]);
    }
#endif  // TC_PATH
}

// ---------------------------------------------------------------------------
// Kernel C: top-budget selection with near-tie fp32 repair + output write.
// ---------------------------------------------------------------------------
__global__ __launch_bounds__(NGROUPS)
void rank_out_kernel(const float* __restrict__ latency,
                     const float* __restrict__ x,
                     const float* __restrict__ bias,
                     const float* __restrict__ u,
                     float* __restrict__ out) {
    __shared__ float kf[NGROUPS];
    __shared__ int   wsum[NGROUPS / 32];
    __shared__ unsigned s_fix[NGROUPS];      // recomputed keys (suspects only)
    __shared__ int   s_list[64];
    __shared__ int   s_n;
    __shared__ float red0[NGROUPS / 32], red1[NGROUPS / 32];

    const int b = blockIdx.x;
    const int t = threadIdx.x;
    const int lane = t & 31, w = t >> 5;

    float units = rintf(latency[b] * 512.0f);
    units = fminf(fmaxf(units, 128.0f), 512.0f);
    const int budget = (int)units - 128;

    unsigned key = __float_as_uint(g_scores[(size_t)b * NGROUPS + t]);
    if (t == 0) s_n = 0;

    // ---- pass 0: binary-search cutoff on approximate keys
    unsigned T = 0u;
#pragma unroll
    for (int bit = 31; bit >= 0; --bit) {
        unsigned cand = T | (1u << bit);
        int c = __syncthreads_count(key >= cand);
        if (c >= budget) T = cand;
    }

    // ---- flag near-tie suspects
    int myidx = -1;
    if (budget > 0) {
        float fT = __uint_as_float(T);
        float fs = __uint_as_float(key);
        if (fabsf(fs - fT) <= MARGIN) {
            int i = atomicAdd(&s_n, 1);
            if (i < 64) { s_list[i] = t; myidx = i; }
        }
    }
    __syncthreads();
    const int nsusp = min(s_n, 64);

    if (nsusp > 0) {
        // ---- exact fp32 recompute of each suspect group's score
        const float* xr = x + (size_t)b * HID;
        for (int si = 0; si < nsusp; ++si) {
            const int g = s_list[si];
            const float* w0 = g_dWn + (size_t)(2 * g) * HID;
            const float* w1 = g_dWn + (size_t)(2 * g + 1) * HID;
            float a = 0.0f, c2 = 0.0f;
            for (int k = t; k < HID; k += NGROUPS) {
                float xv = xr[k];
                a  = fmaf(xv, w0[k], a);
                c2 = fmaf(xv, w1[k], c2);
            }
#pragma unroll
            for (int o = 16; o > 0; o >>= 1) {
                a  += __shfl_down_sync(0xFFFFFFFFu, a, o);
                c2 += __shfl_down_sync(0xFFFFFFFFu, c2, o);
            }
            if (lane == 0) { red0[w] = a; red1[w] = c2; }
            __syncthreads();
            if (t == 0) {
                float la = 0.0f, lb = 0.0f;
#pragma unroll
                for (int ww = 0; ww < NGROUPS / 32; ++ww) { la += red0[ww]; lb += red1[ww]; }
                int n0 = 2 * g, n1 = 2 * g + 1;
                la += bias[2 * n0] - bias[2 * n0 + 1];
                lb += bias[2 * n1] - bias[2 * n1 + 1];
                const float* up = u + (size_t)b * (2 * NCOLS);
                float p0 = sigp(la, up[2 * n0], up[2 * n0 + 1]);
                float p1 = sigp(lb, up[2 * n1], up[2 * n1 + 1]);
                s_fix[g] = __float_as_uint(0.5f * (p0 + p1));
            }
            __syncthreads();
        }
        if (myidx >= 0) key = s_fix[t];

        // ---- pass 1: redo selection on corrected keys
        T = 0u;
#pragma unroll
        for (int bit = 31; bit >= 0; --bit) {
            unsigned cand = T | (1u << bit);
            int c = __syncthreads_count(key >= cand);
            if (c >= budget) T = cand;
        }
    }

    const int cgt  = __syncthreads_count(key > T);
    const int need = budget - cgt;

    const bool eq = (key == T);
    unsigned ball = __ballot_sync(0xFFFFFFFFu, eq);
    if (lane == 0) wsum[w] = __popc(ball);
    __syncthreads();
    int pre = 0;
    for (int ww = 0; ww < w; ww++) pre += wsum[ww];
    const int rank_eq = pre + __popc(ball & ((1u << lane) - 1u));

    const bool keep = (key > T) || (eq && rank_eq < need);
    kf[t] = keep ? 1.0f : 0.0f;
    __syncthreads();

    float* ob = out + (size_t)b * 2048;
    for (int idx = t; idx < 2048; idx += NGROUPS) {
        int l = idx >> 6;
        int h = idx & 31;
        int r = (idx >> 5) & 1;
        float v;
        if (l < 8) {
            v = 1.0f;
        } else {
            float k = kf[(l - 8) * 16 + (h >> 1)];
            v = r ? (1.0f - k) : k;
        }
        ob[idx] = v;
    }
}

// ---------------------------------------------------------------------------
extern "C" void kernel_launch(void* const* d_in, const int* in_sizes, int n_in,
                              void* d_out, int out_size) {
    const float* x       = (const float*)d_in[0];
    const float* latency = (const float*)d_in[1];
    const float* W       = (const float*)d_in[2];
    const float* bias    = (const float*)d_in[3];
    const float* u       = (const float*)d_in[4];
    float* out = (float*)d_out;

    // Variant sniff: tcgen05 build has ~0.8KB static smem; SIMT fallback ~16.6KB.
    size_t dyn = 0;
    int threads = FB_THREADS;
    cudaFuncAttributes fa;
    if (cudaFuncGetAttributes(&fa, gemm_score_kernel) == cudaSuccess &&
        fa.sharedSizeBytes < 8192) {
        cudaFuncSetAttribute(gemm_score_kernel,
                             cudaFuncAttributeMaxDynamicSharedMemorySize, DSMEM_BYTES);
        dyn = DSMEM_BYTES;
        threads = TC_THREADS;
    }

    prep_dw_kernel<<<(HID * NCOLS + 255) / 256, 256>>>(W);
    gemm_score_kernel<<<(NB / BM) * (NCOLS / BN), threads, dyn>>>(x, bias, u);
    rank_out_kernel<<<NB, NGROUPS>>>(latency, x, bias, u, out);
}